// round 1
// baseline (speedup 1.0000x reference)
#include <cuda_runtime.h>

#define NN 50000
#define EE 800000
#define GG 64
#define HD 128
#define BN_EPS 1e-5f

// ---------------- scratch (static device globals; no allocation) ------------
__device__ float g_hs[(size_t)NN * HD];   // GEMM output (pre-scaled by dinv[row])
__device__ float g_agg[(size_t)NN * HD];  // aggregated output (pre-BN)
__device__ float g_y[(size_t)NN * HD];    // post BN+ReLU activations
__device__ float g_dinv[NN];
__device__ int   g_deg[NN];
__device__ int   g_rowptr[NN + 1];
__device__ int   g_cursor[NN];
__device__ int   g_col[EE];
__device__ float g_sum[HD], g_sq[HD];
__device__ float g_a[HD], g_c[HD];
__device__ float g_pool[GG * HD];
__device__ float g_cnt[GG];

// ---------------- graph preprocessing ---------------------------------------
__global__ void k_deg_zero() {
    int i = blockIdx.x * blockDim.x + threadIdx.x;
    if (i < NN) g_deg[i] = 0;
}

__global__ void k_deg_count(const int* __restrict__ dst) {
    int e = blockIdx.x * blockDim.x + threadIdx.x;
    if (e < EE) atomicAdd(&g_deg[dst[e]], 1);
}

// single-block chunked inclusive scan: rowptr + cursor (row starts)
__global__ void k_scan() {
    __shared__ int tmp[1024];
    __shared__ int carry;
    if (threadIdx.x == 0) carry = 0;
    __syncthreads();
    for (int base = 0; base < NN; base += 1024) {
        int i = base + (int)threadIdx.x;
        int v = (i < NN) ? g_deg[i] : 0;
        tmp[threadIdx.x] = v;
        __syncthreads();
        #pragma unroll
        for (int off = 1; off < 1024; off <<= 1) {
            int t = 0;
            if (threadIdx.x >= off) t = tmp[threadIdx.x - off];
            __syncthreads();
            if (threadIdx.x >= off) tmp[threadIdx.x] += t;
            __syncthreads();
        }
        int incl = tmp[threadIdx.x] + carry;
        if (i < NN) {
            g_rowptr[i + 1] = incl;
            g_cursor[i] = incl - v;
        }
        __syncthreads();
        if (threadIdx.x == 1023) carry = incl;
        __syncthreads();
    }
    if (threadIdx.x == 0) g_rowptr[0] = 0;
}

__global__ void k_dinv() {
    int i = blockIdx.x * blockDim.x + threadIdx.x;
    if (i < NN) g_dinv[i] = rsqrtf((float)g_deg[i] + 1.0f);  // +1 self loop
}

__global__ void k_fill(const int* __restrict__ src, const int* __restrict__ dst) {
    int e = blockIdx.x * blockDim.x + threadIdx.x;
    if (e < EE) {
        int d = dst[e];
        int p = atomicAdd(&g_cursor[d], 1);
        g_col[p] = src[e];
    }
}

// ---------------- GEMM: hs[m, :] = (A[m, :] @ W) * dinv[m] ------------------
// A: [M x K] row-major (if A==nullptr, reads g_y), W: [K x 128], out g_hs.
__global__ void k_gemm_dinv(const float* __restrict__ A_in,
                            const float* __restrict__ W, int M, int K) {
    const float* __restrict__ A = A_in ? A_in : g_y;
    __shared__ float sA[16][64];
    __shared__ float sB[16][128];
    int tid = threadIdx.x;          // 256 threads
    int tr = tid >> 4;              // 0..15 thread row
    int tc = tid & 15;              // 0..15 thread col
    int row0 = blockIdx.x * 64;

    float acc[4][8];
    #pragma unroll
    for (int i = 0; i < 4; i++)
        #pragma unroll
        for (int j = 0; j < 8; j++) acc[i][j] = 0.f;

    for (int k0 = 0; k0 < K; k0 += 16) {
        #pragma unroll
        for (int l = 0; l < 4; l++) {
            int idx = tid + l * 256;
            int m = idx >> 4;
            int kk = idx & 15;
            int gm = row0 + m;
            float v = 0.f;
            if (gm < M) v = A[(size_t)gm * K + k0 + kk];
            sA[kk][m] = v;
        }
        #pragma unroll
        for (int l = 0; l < 8; l++) {
            int idx = tid + l * 256;
            int kk = idx >> 7;
            int c = idx & 127;
            sB[kk][c] = W[(k0 + kk) * 128 + c];
        }
        __syncthreads();
        #pragma unroll
        for (int kk = 0; kk < 16; kk++) {
            float ra[4], rb[8];
            #pragma unroll
            for (int i = 0; i < 4; i++) ra[i] = sA[kk][tr * 4 + i];
            #pragma unroll
            for (int j = 0; j < 8; j++) rb[j] = sB[kk][tc * 8 + j];
            #pragma unroll
            for (int i = 0; i < 4; i++)
                #pragma unroll
                for (int j = 0; j < 8; j++) acc[i][j] += ra[i] * rb[j];
        }
        __syncthreads();
    }

    #pragma unroll
    for (int i = 0; i < 4; i++) {
        int m = row0 + tr * 4 + i;
        if (m < M) {
            float di = g_dinv[m];
            #pragma unroll
            for (int j = 0; j < 8; j++)
                g_hs[(size_t)m * 128 + tc * 8 + j] = acc[i][j] * di;
        }
    }
}

// ---------------- aggregation + BN stats ------------------------------------
__global__ void k_zero_stats() {
    g_sum[threadIdx.x] = 0.f;
    g_sq[threadIdx.x] = 0.f;
}

// one warp per node; 8 nodes per block. agg[i] = dinv[i]*(hs[i] + sum hs[nbr]) + b
__global__ void k_agg(const float* __restrict__ b) {
    __shared__ float s_sum[128];
    __shared__ float s_sq[128];
    if (threadIdx.x < 128) { s_sum[threadIdx.x] = 0.f; s_sq[threadIdx.x] = 0.f; }
    __syncthreads();

    int warp = threadIdx.x >> 5;
    int lane = threadIdx.x & 31;
    int i = blockIdx.x * 8 + warp;
    if (i < NN) {
        const float4* __restrict__ hs4 = (const float4*)g_hs;
        float4 acc = hs4[(size_t)i * 32 + lane];   // self term
        int s = g_rowptr[i], e = g_rowptr[i + 1];
        for (int j = s; j < e; j++) {
            int c = g_col[j];
            float4 v = hs4[(size_t)c * 32 + lane];
            acc.x += v.x; acc.y += v.y; acc.z += v.z; acc.w += v.w;
        }
        float di = g_dinv[i];
        float4 bb = ((const float4*)b)[lane];
        float4 o;
        o.x = di * acc.x + bb.x;
        o.y = di * acc.y + bb.y;
        o.z = di * acc.z + bb.z;
        o.w = di * acc.w + bb.w;
        ((float4*)g_agg)[(size_t)i * 32 + lane] = o;

        int f = lane * 4;
        atomicAdd(&s_sum[f + 0], o.x); atomicAdd(&s_sq[f + 0], o.x * o.x);
        atomicAdd(&s_sum[f + 1], o.y); atomicAdd(&s_sq[f + 1], o.y * o.y);
        atomicAdd(&s_sum[f + 2], o.z); atomicAdd(&s_sq[f + 2], o.z * o.z);
        atomicAdd(&s_sum[f + 3], o.w); atomicAdd(&s_sq[f + 3], o.w * o.w);
    }
    __syncthreads();
    if (threadIdx.x < 128) {
        atomicAdd(&g_sum[threadIdx.x], s_sum[threadIdx.x]);
        atomicAdd(&g_sq[threadIdx.x], s_sq[threadIdx.x]);
    }
}

__global__ void k_bnfinal(const float* __restrict__ g, const float* __restrict__ beta) {
    int f = threadIdx.x;
    float mean = g_sum[f] * (1.0f / (float)NN);
    float var = g_sq[f] * (1.0f / (float)NN) - mean * mean;
    float a = g[f] * rsqrtf(var + BN_EPS);
    g_a[f] = a;
    g_c[f] = beta[f] - mean * a;
}

__global__ void k_relunorm() {
    int idx = blockIdx.x * blockDim.x + threadIdx.x;
    const int total = NN * 32;  // float4 count
    for (; idx < total; idx += gridDim.x * blockDim.x) {
        float4 v = ((const float4*)g_agg)[idx];
        int f = (idx & 31) * 4;
        float4 o;
        o.x = fmaxf(fmaf(v.x, g_a[f + 0], g_c[f + 0]), 0.f);
        o.y = fmaxf(fmaf(v.y, g_a[f + 1], g_c[f + 1]), 0.f);
        o.z = fmaxf(fmaf(v.z, g_a[f + 2], g_c[f + 2]), 0.f);
        o.w = fmaxf(fmaf(v.w, g_a[f + 3], g_c[f + 3]), 0.f);
        ((float4*)g_y)[idx] = o;
    }
}

// ---------------- pooling + FC ----------------------------------------------
__global__ void k_pool_zero() {
    int i = blockIdx.x * blockDim.x + threadIdx.x;
    if (i < GG * HD) g_pool[i] = 0.f;
    if (i < GG) g_cnt[i] = 0.f;
}

__global__ void k_pool(const int* __restrict__ batch) {
    int idx = blockIdx.x * blockDim.x + threadIdx.x;
    const int total = NN * 32;
    for (; idx < total; idx += gridDim.x * blockDim.x) {
        int i = idx >> 5;
        int l = idx & 31;
        int g = batch[i];
        float4 v = ((const float4*)g_y)[idx];
        int base = g * 128 + l * 4;
        atomicAdd(&g_pool[base + 0], v.x);
        atomicAdd(&g_pool[base + 1], v.y);
        atomicAdd(&g_pool[base + 2], v.z);
        atomicAdd(&g_pool[base + 3], v.w);
        if (l == 0) atomicAdd(&g_cnt[g], 1.0f);
    }
}

// one block per graph: FC1 (128->256, relu) then FC2 (256->10)
__global__ void k_fc(const float* __restrict__ Wf1, const float* __restrict__ bf1,
                     const float* __restrict__ Wf2, const float* __restrict__ bf2,
                     float* __restrict__ out) {
    __shared__ float sp[128];
    __shared__ float sz[256];
    int g = blockIdx.x;
    int t = threadIdx.x;
    if (t < 128) {
        float cnt = fmaxf(g_cnt[g], 1.0f);
        sp[t] = g_pool[g * 128 + t] / cnt;
    }
    __syncthreads();
    float acc = bf1[t];
    #pragma unroll 8
    for (int k = 0; k < 128; k++) acc = fmaf(sp[k], Wf1[k * 256 + t], acc);
    sz[t] = fmaxf(acc, 0.f);
    __syncthreads();
    if (t < 10) {
        float o = bf2[t];
        #pragma unroll 8
        for (int k = 0; k < 256; k++) o = fmaf(sz[k], Wf2[k * 10 + t], o);
        out[g * 10 + t] = o;
    }
}

// ---------------- launch ------------------------------------------------------
extern "C" void kernel_launch(void* const* d_in, const int* in_sizes, int n_in,
                              void* d_out, int out_size) {
    const float* x     = (const float*)d_in[0];
    const int*   ei    = (const int*)d_in[1];
    const int*   batch = (const int*)d_in[2];
    const float* W1 = (const float*)d_in[3];
    const float* b1 = (const float*)d_in[4];
    const float* g1 = (const float*)d_in[5];
    const float* be1 = (const float*)d_in[6];
    const float* W2 = (const float*)d_in[7];
    const float* b2 = (const float*)d_in[8];
    const float* g2 = (const float*)d_in[9];
    const float* be2 = (const float*)d_in[10];
    const float* W3 = (const float*)d_in[11];
    const float* b3 = (const float*)d_in[12];
    const float* g3 = (const float*)d_in[13];
    const float* be3 = (const float*)d_in[14];
    const float* Wf1 = (const float*)d_in[15];
    const float* bf1 = (const float*)d_in[16];
    const float* Wf2 = (const float*)d_in[17];
    const float* bf2 = (const float*)d_in[18];
    float* out = (float*)d_out;

    const int* src = ei;
    const int* dst = ei + EE;

    // graph preprocessing (CSR by dst + dinv)
    k_deg_zero<<<(NN + 255) / 256, 256>>>();
    k_deg_count<<<(EE + 255) / 256, 256>>>(dst);
    k_scan<<<1, 1024>>>();
    k_dinv<<<(NN + 255) / 256, 256>>>();
    k_fill<<<(EE + 255) / 256, 256>>>(src, dst);

    const int gemm_grid = (NN + 63) / 64;
    const int agg_grid = (NN + 7) / 8;

    // layer 1 (K=96, input x)
    k_gemm_dinv<<<gemm_grid, 256>>>(x, W1, NN, 96);
    k_zero_stats<<<1, 128>>>();
    k_agg<<<agg_grid, 256>>>(b1);
    k_bnfinal<<<1, 128>>>(g1, be1);
    k_relunorm<<<1024, 256>>>();

    // layer 2 (K=128, input g_y)
    k_gemm_dinv<<<gemm_grid, 256>>>(nullptr, W2, NN, 128);
    k_zero_stats<<<1, 128>>>();
    k_agg<<<agg_grid, 256>>>(b2);
    k_bnfinal<<<1, 128>>>(g2, be2);
    k_relunorm<<<1024, 256>>>();

    // layer 3
    k_gemm_dinv<<<gemm_grid, 256>>>(nullptr, W3, NN, 128);
    k_zero_stats<<<1, 128>>>();
    k_agg<<<agg_grid, 256>>>(b3);
    k_bnfinal<<<1, 128>>>(g3, be3);
    k_relunorm<<<1024, 256>>>();

    // pool + FC head
    k_pool_zero<<<(GG * HD + 255) / 256, 256>>>();
    k_pool<<<1024, 256>>>(batch);
    k_fc<<<GG, 256>>>(Wf1, bf1, Wf2, bf2, out);
}

// round 2
// speedup vs baseline: 1.3564x; 1.3564x over previous
#include <cuda_runtime.h>

#define NN 50000
#define EE 800000
#define GG 64
#define HD 128
#define BN_EPS 1e-5f

// ---------------- scratch (static device globals; no allocation) ------------
__device__ float g_hs[(size_t)NN * HD];   // GEMM output (pre-scaled by dinv[row])
__device__ float g_agg[(size_t)NN * HD];  // aggregated output (pre-BN)
__device__ float g_dinv[NN];
__device__ int   g_deg[NN];
__device__ int   g_rowptr[NN + 1];
__device__ int   g_cursor[NN];
__device__ int   g_col[EE];
__device__ float g_sum[HD], g_sq[HD];
__device__ float g_a[HD], g_c[HD];
__device__ float g_pool[GG * HD];
__device__ float g_cnt[GG];

// ---------------- graph preprocessing ---------------------------------------
__global__ void k_deg_zero() {
    int i = blockIdx.x * blockDim.x + threadIdx.x;
    if (i < NN) g_deg[i] = 0;
}

__global__ void k_deg_count(const int* __restrict__ dst) {
    int e = blockIdx.x * blockDim.x + threadIdx.x;
    if (e < EE) atomicAdd(&g_deg[dst[e]], 1);
}

// 1024-thread scan: per-thread serial chunk + one block scan of partials
__global__ void k_scan() {
    __shared__ int part[1024];
    const int CH = (NN + 1023) / 1024;   // 49
    int t = threadIdx.x;
    int s = 0;
    for (int j = 0; j < CH; j++) {
        int i = t * CH + j;
        if (i < NN) s += g_deg[i];
    }
    part[t] = s;
    __syncthreads();
    int own = s;
    #pragma unroll
    for (int off = 1; off < 1024; off <<= 1) {
        int v = 0;
        if (t >= off) v = part[t - off];
        __syncthreads();
        if (t >= off) part[t] += v;
        __syncthreads();
    }
    int run = part[t] - own;   // exclusive prefix
    for (int j = 0; j < CH; j++) {
        int i = t * CH + j;
        if (i < NN) {
            g_cursor[i] = run;
            run += g_deg[i];
            g_rowptr[i + 1] = run;
        }
    }
    if (t == 0) g_rowptr[0] = 0;
}

__global__ void k_dinv() {
    int i = blockIdx.x * blockDim.x + threadIdx.x;
    if (i < NN) g_dinv[i] = rsqrtf((float)g_deg[i] + 1.0f);  // +1 self loop
}

__global__ void k_fill(const int* __restrict__ src, const int* __restrict__ dst) {
    int e = blockIdx.x * blockDim.x + threadIdx.x;
    if (e < EE) {
        int d = dst[e];
        int p = atomicAdd(&g_cursor[d], 1);
        g_col[p] = src[e];
    }
}

// ---------------- tensor-core GEMM (3xTF32) ---------------------------------
// hs[m, :] = (relu(bn(A[m,:])) @ W) * dinv[m]   (bn+relu only when use_bn)
// A: [M x K] row-major (nullptr -> g_agg), W: [K x 128], out g_hs.
// Block tile: 128(M) x 64(N), K-tile 16. 8 warps, warp tile 32x32.

__device__ __forceinline__ unsigned f2tf32(float x) {
    unsigned u;
    asm("cvt.rna.tf32.f32 %0, %1;" : "=r"(u) : "f"(x));
    return u;
}

#define MMA_TF32(c0, c1, c2, c3, a0, a1, a2, a3, b0, b1)                          \
    asm volatile(                                                                 \
        "mma.sync.aligned.m16n8k8.row.col.f32.tf32.tf32.f32 "                     \
        "{%0,%1,%2,%3},{%4,%5,%6,%7},{%8,%9},{%0,%1,%2,%3};"                      \
        : "+f"(c0), "+f"(c1), "+f"(c2), "+f"(c3)                                  \
        : "r"(a0), "r"(a1), "r"(a2), "r"(a3), "r"(b0), "r"(b1))

__global__ __launch_bounds__(256) void k_gemm_tc(
    const float* __restrict__ A_in, const float* __restrict__ W,
    int M, int K, int use_bn) {
    const float* __restrict__ A = A_in ? A_in : g_agg;

    __shared__ float sAh[16 * 129], sAl[16 * 129];
    __shared__ float sBh[16 * 68],  sBl[16 * 68];

    int tid = threadIdx.x;
    int lane = tid & 31, warp = tid >> 5;
    int wm = (warp >> 1) * 32;   // warp M offset within block tile
    int wn = (warp & 1) * 32;    // warp N offset within block tile
    int row0 = blockIdx.x * 128;
    int nb = blockIdx.y * 64;

    float acc[2][4][4];
    #pragma unroll
    for (int mi = 0; mi < 2; mi++)
        #pragma unroll
        for (int ni = 0; ni < 4; ni++)
            #pragma unroll
            for (int q = 0; q < 4; q++) acc[mi][ni][q] = 0.f;

    for (int k0 = 0; k0 < K; k0 += 16) {
        // ---- load A tile (128 x 16), split hi/lo ----
        #pragma unroll
        for (int l = 0; l < 2; l++) {
            int f = tid + l * 256;        // 0..511 float4 slots
            int m = f >> 2;
            int kv = (f & 3) * 4;
            int gm = row0 + m;
            float4 v = make_float4(0.f, 0.f, 0.f, 0.f);
            if (gm < M) v = *(const float4*)&A[(size_t)gm * K + k0 + kv];
            float e[4] = {v.x, v.y, v.z, v.w};
            if (use_bn) {
                #pragma unroll
                for (int q = 0; q < 4; q++) {
                    int kb = k0 + kv + q;
                    e[q] = fmaxf(fmaf(e[q], g_a[kb], g_c[kb]), 0.f);
                }
            }
            #pragma unroll
            for (int q = 0; q < 4; q++) {
                unsigned uh = f2tf32(e[q]);
                float hv = __uint_as_float(uh);
                unsigned ul = f2tf32(e[q] - hv);
                sAh[(kv + q) * 129 + m] = hv;
                sAl[(kv + q) * 129 + m] = __uint_as_float(ul);
            }
        }
        // ---- load B tile (16 x 64), split hi/lo ----
        {
            int kk = tid >> 4;
            int nv = (tid & 15) * 4;
            float4 v = *(const float4*)&W[(size_t)(k0 + kk) * 128 + nb + nv];
            float e[4] = {v.x, v.y, v.z, v.w};
            #pragma unroll
            for (int q = 0; q < 4; q++) {
                unsigned uh = f2tf32(e[q]);
                float hv = __uint_as_float(uh);
                unsigned ul = f2tf32(e[q] - hv);
                sBh[kk * 68 + nv + q] = hv;
                sBl[kk * 68 + nv + q] = __uint_as_float(ul);
            }
        }
        __syncthreads();

        #pragma unroll
        for (int ks = 0; ks < 2; ks++) {
            int kb = ks * 8;
            int kc = kb + (lane & 3);
            unsigned ah[2][4], al[2][4];
            #pragma unroll
            for (int mi = 0; mi < 2; mi++) {
                int r = wm + mi * 16 + (lane >> 2);
                ah[mi][0] = __float_as_uint(sAh[kc * 129 + r]);
                ah[mi][1] = __float_as_uint(sAh[kc * 129 + r + 8]);
                ah[mi][2] = __float_as_uint(sAh[(kc + 4) * 129 + r]);
                ah[mi][3] = __float_as_uint(sAh[(kc + 4) * 129 + r + 8]);
                al[mi][0] = __float_as_uint(sAl[kc * 129 + r]);
                al[mi][1] = __float_as_uint(sAl[kc * 129 + r + 8]);
                al[mi][2] = __float_as_uint(sAl[(kc + 4) * 129 + r]);
                al[mi][3] = __float_as_uint(sAl[(kc + 4) * 129 + r + 8]);
            }
            unsigned bh[4][2], bl[4][2];
            #pragma unroll
            for (int ni = 0; ni < 4; ni++) {
                int n = wn + ni * 8 + (lane >> 2);
                bh[ni][0] = __float_as_uint(sBh[kc * 68 + n]);
                bh[ni][1] = __float_as_uint(sBh[(kc + 4) * 68 + n]);
                bl[ni][0] = __float_as_uint(sBl[kc * 68 + n]);
                bl[ni][1] = __float_as_uint(sBl[(kc + 4) * 68 + n]);
            }
            #pragma unroll
            for (int mi = 0; mi < 2; mi++)
                #pragma unroll
                for (int ni = 0; ni < 4; ni++) {
                    MMA_TF32(acc[mi][ni][0], acc[mi][ni][1], acc[mi][ni][2], acc[mi][ni][3],
                             ah[mi][0], ah[mi][1], ah[mi][2], ah[mi][3],
                             bh[ni][0], bh[ni][1]);
                    MMA_TF32(acc[mi][ni][0], acc[mi][ni][1], acc[mi][ni][2], acc[mi][ni][3],
                             ah[mi][0], ah[mi][1], ah[mi][2], ah[mi][3],
                             bl[ni][0], bl[ni][1]);
                    MMA_TF32(acc[mi][ni][0], acc[mi][ni][1], acc[mi][ni][2], acc[mi][ni][3],
                             al[mi][0], al[mi][1], al[mi][2], al[mi][3],
                             bh[ni][0], bh[ni][1]);
                }
        }
        __syncthreads();
    }

    // ---- epilogue: scale by dinv[row], store ----
    #pragma unroll
    for (int mi = 0; mi < 2; mi++) {
        int r0 = row0 + wm + mi * 16 + (lane >> 2);
        int r1 = r0 + 8;
        float d0 = (r0 < M) ? g_dinv[r0] : 0.f;
        float d1 = (r1 < M) ? g_dinv[r1] : 0.f;
        #pragma unroll
        for (int ni = 0; ni < 4; ni++) {
            int nc = nb + wn + ni * 8 + (lane & 3) * 2;
            if (r0 < M) {
                float2 o = make_float2(acc[mi][ni][0] * d0, acc[mi][ni][1] * d0);
                *(float2*)&g_hs[(size_t)r0 * 128 + nc] = o;
            }
            if (r1 < M) {
                float2 o = make_float2(acc[mi][ni][2] * d1, acc[mi][ni][3] * d1);
                *(float2*)&g_hs[(size_t)r1 * 128 + nc] = o;
            }
        }
    }
}

// ---------------- aggregation + BN stats ------------------------------------
__global__ void k_zero_stats() {
    g_sum[threadIdx.x] = 0.f;
    g_sq[threadIdx.x] = 0.f;
}

// one warp per node; 8 nodes/block. agg[i] = dinv[i]*(hs[i] + sum hs[nbr]) + b
__global__ void k_agg(const float* __restrict__ b) {
    __shared__ float s_sum[128];
    __shared__ float s_sq[128];
    if (threadIdx.x < 128) { s_sum[threadIdx.x] = 0.f; s_sq[threadIdx.x] = 0.f; }
    __syncthreads();

    int warp = threadIdx.x >> 5;
    int lane = threadIdx.x & 31;
    int i = blockIdx.x * 8 + warp;
    if (i < NN) {
        const float4* __restrict__ hs4 = (const float4*)g_hs;
        float4 a0 = hs4[(size_t)i * 32 + lane];   // self term
        float4 a1 = make_float4(0, 0, 0, 0);
        float4 a2 = make_float4(0, 0, 0, 0);
        float4 a3 = make_float4(0, 0, 0, 0);
        int s = g_rowptr[i], e = g_rowptr[i + 1];
        int j = s;
        for (; j + 4 <= e; j += 4) {
            int c0 = g_col[j], c1 = g_col[j + 1], c2 = g_col[j + 2], c3 = g_col[j + 3];
            float4 v0 = hs4[(size_t)c0 * 32 + lane];
            float4 v1 = hs4[(size_t)c1 * 32 + lane];
            float4 v2 = hs4[(size_t)c2 * 32 + lane];
            float4 v3 = hs4[(size_t)c3 * 32 + lane];
            a0.x += v0.x; a0.y += v0.y; a0.z += v0.z; a0.w += v0.w;
            a1.x += v1.x; a1.y += v1.y; a1.z += v1.z; a1.w += v1.w;
            a2.x += v2.x; a2.y += v2.y; a2.z += v2.z; a2.w += v2.w;
            a3.x += v3.x; a3.y += v3.y; a3.z += v3.z; a3.w += v3.w;
        }
        for (; j < e; j++) {
            int c = g_col[j];
            float4 v = hs4[(size_t)c * 32 + lane];
            a0.x += v.x; a0.y += v.y; a0.z += v.z; a0.w += v.w;
        }
        float4 acc;
        acc.x = (a0.x + a1.x) + (a2.x + a3.x);
        acc.y = (a0.y + a1.y) + (a2.y + a3.y);
        acc.z = (a0.z + a1.z) + (a2.z + a3.z);
        acc.w = (a0.w + a1.w) + (a2.w + a3.w);
        float di = g_dinv[i];
        float4 bb = ((const float4*)b)[lane];
        float4 o;
        o.x = di * acc.x + bb.x;
        o.y = di * acc.y + bb.y;
        o.z = di * acc.z + bb.z;
        o.w = di * acc.w + bb.w;
        ((float4*)g_agg)[(size_t)i * 32 + lane] = o;

        int f = lane * 4;
        atomicAdd(&s_sum[f + 0], o.x); atomicAdd(&s_sq[f + 0], o.x * o.x);
        atomicAdd(&s_sum[f + 1], o.y); atomicAdd(&s_sq[f + 1], o.y * o.y);
        atomicAdd(&s_sum[f + 2], o.z); atomicAdd(&s_sq[f + 2], o.z * o.z);
        atomicAdd(&s_sum[f + 3], o.w); atomicAdd(&s_sq[f + 3], o.w * o.w);
    }
    __syncthreads();
    if (threadIdx.x < 128) {
        atomicAdd(&g_sum[threadIdx.x], s_sum[threadIdx.x]);
        atomicAdd(&g_sq[threadIdx.x], s_sq[threadIdx.x]);
    }
}

__global__ void k_bnfinal(const float* __restrict__ g, const float* __restrict__ beta) {
    int f = threadIdx.x;
    float mean = g_sum[f] * (1.0f / (float)NN);
    float var = g_sq[f] * (1.0f / (float)NN) - mean * mean;
    float a = g[f] * rsqrtf(var + BN_EPS);
    g_a[f] = a;
    g_c[f] = beta[f] - mean * a;
}

// ---------------- pooling (applies layer-3 BN+ReLU inline) ------------------
__global__ void k_pool_zero() {
    int i = blockIdx.x * blockDim.x + threadIdx.x;
    if (i < GG * HD) g_pool[i] = 0.f;
    if (i < GG) g_cnt[i] = 0.f;
}

// batch is sorted: each warp walks 32 consecutive nodes, register-accumulates
// runs, flushes on graph change. 8 warps/block -> 256 nodes/block.
__global__ void k_pool(const int* __restrict__ batch) {
    int warp = threadIdx.x >> 5;
    int lane = threadIdx.x & 31;
    int i0 = blockIdx.x * 256 + warp * 32;
    int f = lane * 4;
    float a0 = g_a[f + 0], a1 = g_a[f + 1], a2 = g_a[f + 2], a3 = g_a[f + 3];
    float c0 = g_c[f + 0], c1 = g_c[f + 1], c2 = g_c[f + 2], c3 = g_c[f + 3];

    float4 acc = make_float4(0, 0, 0, 0);
    int cur = -1, run = 0;
    for (int t = 0; t < 32; t++) {
        int i = i0 + t;
        if (i >= NN) break;
        int g = batch[i];
        if (g != cur) {
            if (cur >= 0) {
                int base = cur * 128 + f;
                atomicAdd(&g_pool[base + 0], acc.x);
                atomicAdd(&g_pool[base + 1], acc.y);
                atomicAdd(&g_pool[base + 2], acc.z);
                atomicAdd(&g_pool[base + 3], acc.w);
                if (lane == 0) atomicAdd(&g_cnt[cur], (float)run);
            }
            cur = g; run = 0;
            acc = make_float4(0, 0, 0, 0);
        }
        float4 v = ((const float4*)g_agg)[(size_t)i * 32 + lane];
        acc.x += fmaxf(fmaf(v.x, a0, c0), 0.f);
        acc.y += fmaxf(fmaf(v.y, a1, c1), 0.f);
        acc.z += fmaxf(fmaf(v.z, a2, c2), 0.f);
        acc.w += fmaxf(fmaf(v.w, a3, c3), 0.f);
        run++;
    }
    if (cur >= 0) {
        int base = cur * 128 + f;
        atomicAdd(&g_pool[base + 0], acc.x);
        atomicAdd(&g_pool[base + 1], acc.y);
        atomicAdd(&g_pool[base + 2], acc.z);
        atomicAdd(&g_pool[base + 3], acc.w);
        if (lane == 0) atomicAdd(&g_cnt[cur], (float)run);
    }
}

// one block per graph: FC1 (128->256, relu) then FC2 (256->10)
__global__ void k_fc(const float* __restrict__ Wf1, const float* __restrict__ bf1,
                     const float* __restrict__ Wf2, const float* __restrict__ bf2,
                     float* __restrict__ out) {
    __shared__ float sp[128];
    __shared__ float sz[256];
    int g = blockIdx.x;
    int t = threadIdx.x;
    if (t < 128) {
        float cnt = fmaxf(g_cnt[g], 1.0f);
        sp[t] = g_pool[g * 128 + t] / cnt;
    }
    __syncthreads();
    float acc = bf1[t];
    #pragma unroll 8
    for (int k = 0; k < 128; k++) acc = fmaf(sp[k], Wf1[k * 256 + t], acc);
    sz[t] = fmaxf(acc, 0.f);
    __syncthreads();
    if (t < 10) {
        float o = bf2[t];
        #pragma unroll 8
        for (int k = 0; k < 256; k++) o = fmaf(sz[k], Wf2[k * 10 + t], o);
        out[g * 10 + t] = o;
    }
}

// ---------------- launch ------------------------------------------------------
extern "C" void kernel_launch(void* const* d_in, const int* in_sizes, int n_in,
                              void* d_out, int out_size) {
    const float* x     = (const float*)d_in[0];
    const int*   ei    = (const int*)d_in[1];
    const int*   batch = (const int*)d_in[2];
    const float* W1 = (const float*)d_in[3];
    const float* b1 = (const float*)d_in[4];
    const float* g1 = (const float*)d_in[5];
    const float* be1 = (const float*)d_in[6];
    const float* W2 = (const float*)d_in[7];
    const float* b2 = (const float*)d_in[8];
    const float* g2 = (const float*)d_in[9];
    const float* be2 = (const float*)d_in[10];
    const float* W3 = (const float*)d_in[11];
    const float* b3 = (const float*)d_in[12];
    const float* g3 = (const float*)d_in[13];
    const float* be3 = (const float*)d_in[14];
    const float* Wf1 = (const float*)d_in[15];
    const float* bf1 = (const float*)d_in[16];
    const float* Wf2 = (const float*)d_in[17];
    const float* bf2 = (const float*)d_in[18];
    float* out = (float*)d_out;

    const int* src = ei;
    const int* dst = ei + EE;

    // graph preprocessing (CSR by dst + dinv)
    k_deg_zero<<<(NN + 255) / 256, 256>>>();
    k_deg_count<<<(EE + 255) / 256, 256>>>(dst);
    k_scan<<<1, 1024>>>();
    k_dinv<<<(NN + 255) / 256, 256>>>();
    k_fill<<<(EE + 255) / 256, 256>>>(src, dst);

    dim3 gemm_grid((NN + 127) / 128, 2);
    const int agg_grid = (NN + 7) / 8;

    // layer 1 (K=96, input x, no BN on input)
    k_gemm_tc<<<gemm_grid, 256>>>(x, W1, NN, 96, 0);
    k_zero_stats<<<1, 128>>>();
    k_agg<<<agg_grid, 256>>>(b1);
    k_bnfinal<<<1, 128>>>(g1, be1);

    // layer 2 (K=128, input g_agg with BN1+ReLU applied inline)
    k_gemm_tc<<<gemm_grid, 256>>>(nullptr, W2, NN, 128, 1);
    k_zero_stats<<<1, 128>>>();
    k_agg<<<agg_grid, 256>>>(b2);
    k_bnfinal<<<1, 128>>>(g2, be2);

    // layer 3
    k_gemm_tc<<<gemm_grid, 256>>>(nullptr, W3, NN, 128, 1);
    k_zero_stats<<<1, 128>>>();
    k_agg<<<agg_grid, 256>>>(b3);
    k_bnfinal<<<1, 128>>>(g3, be3);

    // pool (BN3+ReLU inline) + FC head
    k_pool_zero<<<(GG * HD + 255) / 256, 256>>>();
    k_pool<<<(NN + 255) / 256, 256>>>(batch);
    k_fc<<<GG, 256>>>(Wf1, bf1, Wf2, bf2, out);
}

// round 3
// speedup vs baseline: 2.1100x; 1.5556x over previous
#include <cuda_runtime.h>
#include <cuda_bf16.h>

#define NN 50000
#define EE 800000
#define GG 64
#define BN_EPS 1e-5f

// ---------------- scratch (static device globals; no allocation) ------------
__device__ float g_hs[(size_t)NN * 128];   // GEMM output (pre-scaled by dinv[row])
__device__ float g_agg[(size_t)NN * 128];  // aggregated output (pre-BN)
__device__ float g_dinv[NN];
__device__ int   g_deg[NN];
__device__ int   g_rowptr[NN + 1];
__device__ int   g_cursor[NN];
__device__ int   g_col[EE];
__device__ float g_sumA[3][128], g_sqA[3][128];
__device__ float g_pool[GG * 128];
__device__ float g_cnt[GG];

// ---------------- init: zero everything in one launch ------------------------
__global__ void k_init() {
    int i = blockIdx.x * blockDim.x + threadIdx.x;
    if (i < NN) g_deg[i] = 0;
    if (i < 128) {
        #pragma unroll
        for (int l = 0; l < 3; l++) { g_sumA[l][i] = 0.f; g_sqA[l][i] = 0.f; }
    }
    if (i < GG * 128) g_pool[i] = 0.f;
    if (i < GG) g_cnt[i] = 0.f;
}

__global__ void k_deg_count(const int* __restrict__ dst) {
    int e = blockIdx.x * blockDim.x + threadIdx.x;
    if (e < EE) atomicAdd(&g_deg[dst[e]], 1);
}

// 1024-thread scan: per-thread serial chunk + block scan; also computes dinv
__global__ void k_scan() {
    __shared__ int part[1024];
    const int CH = (NN + 1023) / 1024;
    int t = threadIdx.x;
    int s = 0;
    for (int j = 0; j < CH; j++) {
        int i = t * CH + j;
        if (i < NN) s += g_deg[i];
    }
    part[t] = s;
    __syncthreads();
    int own = s;
    #pragma unroll
    for (int off = 1; off < 1024; off <<= 1) {
        int v = 0;
        if (t >= off) v = part[t - off];
        __syncthreads();
        if (t >= off) part[t] += v;
        __syncthreads();
    }
    int run = part[t] - own;
    for (int j = 0; j < CH; j++) {
        int i = t * CH + j;
        if (i < NN) {
            int d = g_deg[i];
            g_cursor[i] = run;
            run += d;
            g_rowptr[i + 1] = run;
            g_dinv[i] = rsqrtf((float)d + 1.0f);   // +1 self loop
        }
    }
    if (t == 0) g_rowptr[0] = 0;
}

__global__ void k_fill(const int* __restrict__ src, const int* __restrict__ dst) {
    int e = blockIdx.x * blockDim.x + threadIdx.x;
    if (e < EE) {
        int d = dst[e];
        int p = atomicAdd(&g_cursor[d], 1);
        g_col[p] = src[e];
    }
}

// ---------------- tensor-core GEMM (bf16x2 split, m16n8k16) -----------------
// hs[m,:] = (relu(bn(A[m,:])) @ W) * dinv[m]; bn computed from gsum/gsq inline.
// Block tile 128(M) x 128(N), K-tile 16, 512 threads (16 warps, warp 32x32).

__device__ __forceinline__ void bsplit2(float x0, float x1, unsigned& hi, unsigned& lo) {
    __nv_bfloat16 h0 = __float2bfloat16(x0);
    __nv_bfloat16 h1 = __float2bfloat16(x1);
    float r0 = x0 - __bfloat162float(h0);
    float r1 = x1 - __bfloat162float(h1);
    __nv_bfloat16 l0 = __float2bfloat16(r0);
    __nv_bfloat16 l1 = __float2bfloat16(r1);
    hi = ((unsigned)__bfloat16_as_ushort(h1) << 16) | (unsigned)__bfloat16_as_ushort(h0);
    lo = ((unsigned)__bfloat16_as_ushort(l1) << 16) | (unsigned)__bfloat16_as_ushort(l0);
}

#define MMA_BF16(C, a0, a1, a2, a3, b0, b1)                                        \
    asm volatile(                                                                  \
        "mma.sync.aligned.m16n8k16.row.col.f32.bf16.bf16.f32 "                     \
        "{%0,%1,%2,%3},{%4,%5,%6,%7},{%8,%9},{%0,%1,%2,%3};"                       \
        : "+f"((C)[0]), "+f"((C)[1]), "+f"((C)[2]), "+f"((C)[3])                   \
        : "r"(a0), "r"(a1), "r"(a2), "r"(a3), "r"(b0), "r"(b1))

#define SA 136   // stride ≡ 8 (mod 32) → conflict-free fragment reads

__global__ __launch_bounds__(512) void k_gemm(
    const float* __restrict__ A_in, const float* __restrict__ W, int M, int K,
    const float* __restrict__ gsum, const float* __restrict__ gsq,
    const float* __restrict__ gamma, const float* __restrict__ beta) {
    const float* __restrict__ A = A_in ? A_in : g_agg;
    __shared__ unsigned sAh[8 * SA], sAl[8 * SA], sBh[8 * SA], sBl[8 * SA];
    __shared__ float sa[128], sc[128];

    int tid = threadIdx.x, lane = tid & 31, warp = tid >> 5;
    int use_bn = (gsum != nullptr);
    if (use_bn && tid < 128) {
        float mean = gsum[tid] * (1.0f / (float)NN);
        float var = gsq[tid] * (1.0f / (float)NN) - mean * mean;
        float a = gamma[tid] * rsqrtf(var + BN_EPS);
        sa[tid] = a;
        sc[tid] = beta[tid] - mean * a;
    }
    __syncthreads();

    int row0 = blockIdx.x * 128;
    int wm = (warp >> 2) * 32;
    int wn = (warp & 3) * 32;

    float acc[2][4][4];
    #pragma unroll
    for (int mi = 0; mi < 2; mi++)
        #pragma unroll
        for (int ni = 0; ni < 4; ni++)
            #pragma unroll
            for (int q = 0; q < 4; q++) acc[mi][ni][q] = 0.f;

    for (int k0 = 0; k0 < K; k0 += 16) {
        // ---- A tile (128 x 16): 1 float4 per thread ----
        {
            int m = tid >> 2, kv = (tid & 3) * 4, gm = row0 + m;
            float4 v = make_float4(0.f, 0.f, 0.f, 0.f);
            if (gm < M) v = *(const float4*)&A[(size_t)gm * K + k0 + kv];
            float e[4] = {v.x, v.y, v.z, v.w};
            if (use_bn) {
                #pragma unroll
                for (int q = 0; q < 4; q++) {
                    int kb = k0 + kv + q;
                    e[q] = fmaxf(fmaf(e[q], sa[kb], sc[kb]), 0.f);
                }
            }
            unsigned h0, l0, h1, l1;
            bsplit2(e[0], e[1], h0, l0);
            bsplit2(e[2], e[3], h1, l1);
            int k2 = kv >> 1;
            sAh[k2 * SA + m] = h0;       sAl[k2 * SA + m] = l0;
            sAh[(k2 + 1) * SA + m] = h1; sAl[(k2 + 1) * SA + m] = l1;
        }
        // ---- B tile (16 x 128): 2 cols x 2 rows per thread ----
        {
            int k2 = tid >> 6, n2 = (tid & 63) * 2;
            float2 w0 = *(const float2*)&W[(size_t)(k0 + k2 * 2) * 128 + n2];
            float2 w1 = *(const float2*)&W[(size_t)(k0 + k2 * 2 + 1) * 128 + n2];
            unsigned h, l;
            bsplit2(w0.x, w1.x, h, l);
            sBh[k2 * SA + n2] = h; sBl[k2 * SA + n2] = l;
            bsplit2(w0.y, w1.y, h, l);
            sBh[k2 * SA + n2 + 1] = h; sBl[k2 * SA + n2 + 1] = l;
        }
        __syncthreads();

        unsigned ah[2][4], al[2][4];
        int kq = lane & 3;
        #pragma unroll
        for (int mi = 0; mi < 2; mi++) {
            int r = wm + mi * 16 + (lane >> 2);
            ah[mi][0] = sAh[kq * SA + r];       ah[mi][1] = sAh[kq * SA + r + 8];
            ah[mi][2] = sAh[(kq + 4) * SA + r]; ah[mi][3] = sAh[(kq + 4) * SA + r + 8];
            al[mi][0] = sAl[kq * SA + r];       al[mi][1] = sAl[kq * SA + r + 8];
            al[mi][2] = sAl[(kq + 4) * SA + r]; al[mi][3] = sAl[(kq + 4) * SA + r + 8];
        }
        #pragma unroll
        for (int ni = 0; ni < 4; ni++) {
            int n = wn + ni * 8 + (lane >> 2);
            unsigned bh0 = sBh[kq * SA + n], bh1 = sBh[(kq + 4) * SA + n];
            unsigned bl0 = sBl[kq * SA + n], bl1 = sBl[(kq + 4) * SA + n];
            #pragma unroll
            for (int mi = 0; mi < 2; mi++) {
                MMA_BF16(acc[mi][ni], ah[mi][0], ah[mi][1], ah[mi][2], ah[mi][3], bh0, bh1);
                MMA_BF16(acc[mi][ni], ah[mi][0], ah[mi][1], ah[mi][2], ah[mi][3], bl0, bl1);
                MMA_BF16(acc[mi][ni], al[mi][0], al[mi][1], al[mi][2], al[mi][3], bh0, bh1);
            }
        }
        __syncthreads();
    }

    // ---- epilogue: scale by dinv[row], store float2 ----
    #pragma unroll
    for (int mi = 0; mi < 2; mi++) {
        int r0 = row0 + wm + mi * 16 + (lane >> 2);
        int r1 = r0 + 8;
        float d0 = (r0 < M) ? g_dinv[r0] : 0.f;
        float d1 = (r1 < M) ? g_dinv[r1] : 0.f;
        #pragma unroll
        for (int ni = 0; ni < 4; ni++) {
            int nc = wn + ni * 8 + (lane & 3) * 2;
            if (r0 < M)
                *(float2*)&g_hs[(size_t)r0 * 128 + nc] =
                    make_float2(acc[mi][ni][0] * d0, acc[mi][ni][1] * d0);
            if (r1 < M)
                *(float2*)&g_hs[(size_t)r1 * 128 + nc] =
                    make_float2(acc[mi][ni][2] * d1, acc[mi][ni][3] * d1);
        }
    }
}

// ---------------- aggregation + BN stats (4 nodes per warp) -----------------
__global__ void k_agg(const float* __restrict__ b,
                      float* __restrict__ gsum, float* __restrict__ gsq) {
    __shared__ float s_sum[128];
    __shared__ float s_sq[128];
    if (threadIdx.x < 128) { s_sum[threadIdx.x] = 0.f; s_sq[threadIdx.x] = 0.f; }
    __syncthreads();

    int warp = threadIdx.x >> 5;
    int lane = threadIdx.x & 31;
    const float4* __restrict__ hs4 = (const float4*)g_hs;
    float4 bb = ((const float4*)b)[lane];
    float4 ss = make_float4(0, 0, 0, 0), qq = make_float4(0, 0, 0, 0);

    int i0 = (blockIdx.x * 8 + warp) * 4;
    #pragma unroll
    for (int t = 0; t < 4; t++) {
        int i = i0 + t;
        if (i >= NN) break;
        float4 a0 = hs4[(size_t)i * 32 + lane];   // self term
        float4 a1 = make_float4(0, 0, 0, 0);
        float4 a2 = make_float4(0, 0, 0, 0);
        float4 a3 = make_float4(0, 0, 0, 0);
        int s = g_rowptr[i], e = g_rowptr[i + 1];
        int j = s;
        for (; j + 4 <= e; j += 4) {
            int c0 = g_col[j], c1 = g_col[j + 1], c2 = g_col[j + 2], c3 = g_col[j + 3];
            float4 v0 = hs4[(size_t)c0 * 32 + lane];
            float4 v1 = hs4[(size_t)c1 * 32 + lane];
            float4 v2 = hs4[(size_t)c2 * 32 + lane];
            float4 v3 = hs4[(size_t)c3 * 32 + lane];
            a0.x += v0.x; a0.y += v0.y; a0.z += v0.z; a0.w += v0.w;
            a1.x += v1.x; a1.y += v1.y; a1.z += v1.z; a1.w += v1.w;
            a2.x += v2.x; a2.y += v2.y; a2.z += v2.z; a2.w += v2.w;
            a3.x += v3.x; a3.y += v3.y; a3.z += v3.z; a3.w += v3.w;
        }
        for (; j < e; j++) {
            int c = g_col[j];
            float4 v = hs4[(size_t)c * 32 + lane];
            a0.x += v.x; a0.y += v.y; a0.z += v.z; a0.w += v.w;
        }
        float di = g_dinv[i];
        float4 o;
        o.x = di * ((a0.x + a1.x) + (a2.x + a3.x)) + bb.x;
        o.y = di * ((a0.y + a1.y) + (a2.y + a3.y)) + bb.y;
        o.z = di * ((a0.z + a1.z) + (a2.z + a3.z)) + bb.z;
        o.w = di * ((a0.w + a1.w) + (a2.w + a3.w)) + bb.w;
        ((float4*)g_agg)[(size_t)i * 32 + lane] = o;
        ss.x += o.x; ss.y += o.y; ss.z += o.z; ss.w += o.w;
        qq.x += o.x * o.x; qq.y += o.y * o.y; qq.z += o.z * o.z; qq.w += o.w * o.w;
    }

    int f = lane * 4;
    atomicAdd(&s_sum[f + 0], ss.x); atomicAdd(&s_sq[f + 0], qq.x);
    atomicAdd(&s_sum[f + 1], ss.y); atomicAdd(&s_sq[f + 1], qq.y);
    atomicAdd(&s_sum[f + 2], ss.z); atomicAdd(&s_sq[f + 2], qq.z);
    atomicAdd(&s_sum[f + 3], ss.w); atomicAdd(&s_sq[f + 3], qq.w);
    __syncthreads();
    if (threadIdx.x < 128) {
        atomicAdd(&gsum[threadIdx.x], s_sum[threadIdx.x]);
        atomicAdd(&gsq[threadIdx.x], s_sq[threadIdx.x]);
    }
}

// ---------------- pooling (layer-3 BN+ReLU inline, BN computed in-block) ----
__global__ void k_pool(const int* __restrict__ batch,
                       const float* __restrict__ gsum, const float* __restrict__ gsq,
                       const float* __restrict__ gamma, const float* __restrict__ beta) {
    __shared__ float sa[128], sc[128];
    if (threadIdx.x < 128) {
        float mean = gsum[threadIdx.x] * (1.0f / (float)NN);
        float var = gsq[threadIdx.x] * (1.0f / (float)NN) - mean * mean;
        float a = gamma[threadIdx.x] * rsqrtf(var + BN_EPS);
        sa[threadIdx.x] = a;
        sc[threadIdx.x] = beta[threadIdx.x] - mean * a;
    }
    __syncthreads();

    int warp = threadIdx.x >> 5;
    int lane = threadIdx.x & 31;
    int i0 = blockIdx.x * 256 + warp * 32;
    int f = lane * 4;
    float a0 = sa[f + 0], a1 = sa[f + 1], a2 = sa[f + 2], a3 = sa[f + 3];
    float c0 = sc[f + 0], c1 = sc[f + 1], c2 = sc[f + 2], c3 = sc[f + 3];

    float4 acc = make_float4(0, 0, 0, 0);
    int cur = -1, run = 0;
    for (int t = 0; t < 32; t++) {
        int i = i0 + t;
        if (i >= NN) break;
        int g = batch[i];
        if (g != cur) {
            if (cur >= 0) {
                int base = cur * 128 + f;
                atomicAdd(&g_pool[base + 0], acc.x);
                atomicAdd(&g_pool[base + 1], acc.y);
                atomicAdd(&g_pool[base + 2], acc.z);
                atomicAdd(&g_pool[base + 3], acc.w);
                if (lane == 0) atomicAdd(&g_cnt[cur], (float)run);
            }
            cur = g; run = 0;
            acc = make_float4(0, 0, 0, 0);
        }
        float4 v = ((const float4*)g_agg)[(size_t)i * 32 + lane];
        acc.x += fmaxf(fmaf(v.x, a0, c0), 0.f);
        acc.y += fmaxf(fmaf(v.y, a1, c1), 0.f);
        acc.z += fmaxf(fmaf(v.z, a2, c2), 0.f);
        acc.w += fmaxf(fmaf(v.w, a3, c3), 0.f);
        run++;
    }
    if (cur >= 0) {
        int base = cur * 128 + f;
        atomicAdd(&g_pool[base + 0], acc.x);
        atomicAdd(&g_pool[base + 1], acc.y);
        atomicAdd(&g_pool[base + 2], acc.z);
        atomicAdd(&g_pool[base + 3], acc.w);
        if (lane == 0) atomicAdd(&g_cnt[cur], (float)run);
    }
}

// one block per graph: FC1 (128->256, relu) then FC2 (256->10)
__global__ void k_fc(const float* __restrict__ Wf1, const float* __restrict__ bf1,
                     const float* __restrict__ Wf2, const float* __restrict__ bf2,
                     float* __restrict__ out) {
    __shared__ float sp[128];
    __shared__ float sz[256];
    int g = blockIdx.x;
    int t = threadIdx.x;
    if (t < 128) {
        float cnt = fmaxf(g_cnt[g], 1.0f);
        sp[t] = g_pool[g * 128 + t] / cnt;
    }
    __syncthreads();
    float acc = bf1[t];
    #pragma unroll 8
    for (int k = 0; k < 128; k++) acc = fmaf(sp[k], Wf1[k * 256 + t], acc);
    sz[t] = fmaxf(acc, 0.f);
    __syncthreads();
    if (t < 10) {
        float o = bf2[t];
        #pragma unroll 8
        for (int k = 0; k < 256; k++) o = fmaf(sz[k], Wf2[k * 10 + t], o);
        out[g * 10 + t] = o;
    }
}

// ---------------- launch ------------------------------------------------------
extern "C" void kernel_launch(void* const* d_in, const int* in_sizes, int n_in,
                              void* d_out, int out_size) {
    const float* x     = (const float*)d_in[0];
    const int*   ei    = (const int*)d_in[1];
    const int*   batch = (const int*)d_in[2];
    const float* W1 = (const float*)d_in[3];
    const float* b1 = (const float*)d_in[4];
    const float* g1 = (const float*)d_in[5];
    const float* be1 = (const float*)d_in[6];
    const float* W2 = (const float*)d_in[7];
    const float* b2 = (const float*)d_in[8];
    const float* g2 = (const float*)d_in[9];
    const float* be2 = (const float*)d_in[10];
    const float* W3 = (const float*)d_in[11];
    const float* b3 = (const float*)d_in[12];
    const float* g3 = (const float*)d_in[13];
    const float* be3 = (const float*)d_in[14];
    const float* Wf1 = (const float*)d_in[15];
    const float* bf1 = (const float*)d_in[16];
    const float* Wf2 = (const float*)d_in[17];
    const float* bf2 = (const float*)d_in[18];
    float* out = (float*)d_out;

    const int* src = ei;
    const int* dst = ei + EE;

    float* sum0; float* sq0; float* sum1; float* sq1; float* sum2; float* sq2;
    cudaGetSymbolAddress((void**)&sum0, g_sumA);
    cudaGetSymbolAddress((void**)&sq0, g_sqA);
    sum1 = sum0 + 128; sum2 = sum0 + 256;
    sq1 = sq0 + 128; sq2 = sq0 + 256;

    // preprocessing
    k_init<<<(NN + 255) / 256, 256>>>();
    k_deg_count<<<(EE + 255) / 256, 256>>>(dst);
    k_scan<<<1, 1024>>>();
    k_fill<<<(EE + 255) / 256, 256>>>(src, dst);

    const int gemm_grid = (NN + 127) / 128;
    const int agg_grid = (NN + 31) / 32;

    // layer 1 (K=96, input x, no BN)
    k_gemm<<<gemm_grid, 512>>>(x, W1, NN, 96, nullptr, nullptr, nullptr, nullptr);
    k_agg<<<agg_grid, 256>>>(b1, sum0, sq0);

    // layer 2 (BN1+ReLU fused into A-load)
    k_gemm<<<gemm_grid, 512>>>(nullptr, W2, NN, 128, sum0, sq0, g1, be1);
    k_agg<<<agg_grid, 256>>>(b2, sum1, sq1);

    // layer 3
    k_gemm<<<gemm_grid, 512>>>(nullptr, W3, NN, 128, sum1, sq1, g2, be2);
    k_agg<<<agg_grid, 256>>>(b3, sum2, sq2);

    // pool (BN3+ReLU inline) + FC head
    k_pool<<<(NN + 255) / 256, 256>>>(batch, sum2, sq2, g3, be3);
    k_fc<<<GG, 256>>>(Wf1, bf1, Wf2, bf2, out);
}

// round 4
// speedup vs baseline: 2.1971x; 1.0413x over previous
#include <cuda_runtime.h>
#include <cuda_bf16.h>
#include <cuda_fp16.h>

#define NN 50000
#define EE 800000
#define GG 64
#define BN_EPS 1e-5f

// ---------------- scratch (static device globals; no allocation) ------------
__device__ __half g_hs[(size_t)NN * 128];  // GEMM output (pre-scaled by dinv[row]), fp16
__device__ float g_agg[(size_t)NN * 128];  // aggregated output (pre-BN), fp32
__device__ float g_dinv[NN];
__device__ int   g_deg[NN];
__device__ int   g_rowptr[NN + 1];
__device__ int   g_cursor[NN];
__device__ int   g_col[EE];
__device__ float g_sumA[3][128], g_sqA[3][128];
__device__ float g_pool[GG * 128];
__device__ float g_cnt[GG];

// ---------------- init: zero everything in one launch ------------------------
__global__ void k_init() {
    int i = blockIdx.x * blockDim.x + threadIdx.x;
    if (i < NN) g_deg[i] = 0;
    if (i < 128) {
        #pragma unroll
        for (int l = 0; l < 3; l++) { g_sumA[l][i] = 0.f; g_sqA[l][i] = 0.f; }
    }
    if (i < GG * 128) g_pool[i] = 0.f;
    if (i < GG) g_cnt[i] = 0.f;
}

__global__ void k_deg_count(const int* __restrict__ dst) {
    int e = blockIdx.x * blockDim.x + threadIdx.x;
    if (e < EE) atomicAdd(&g_deg[dst[e]], 1);
}

// 1024-thread scan: per-thread serial chunk + block scan; also computes dinv
__global__ void k_scan() {
    __shared__ int part[1024];
    const int CH = (NN + 1023) / 1024;
    int t = threadIdx.x;
    int s = 0;
    for (int j = 0; j < CH; j++) {
        int i = t * CH + j;
        if (i < NN) s += g_deg[i];
    }
    part[t] = s;
    __syncthreads();
    int own = s;
    #pragma unroll
    for (int off = 1; off < 1024; off <<= 1) {
        int v = 0;
        if (t >= off) v = part[t - off];
        __syncthreads();
        if (t >= off) part[t] += v;
        __syncthreads();
    }
    int run = part[t] - own;
    for (int j = 0; j < CH; j++) {
        int i = t * CH + j;
        if (i < NN) {
            int d = g_deg[i];
            g_cursor[i] = run;
            run += d;
            g_rowptr[i + 1] = run;
            g_dinv[i] = rsqrtf((float)d + 1.0f);   // +1 self loop
        }
    }
    if (t == 0) g_rowptr[0] = 0;
}

__global__ void k_fill(const int* __restrict__ src, const int* __restrict__ dst) {
    int e = blockIdx.x * blockDim.x + threadIdx.x;
    if (e < EE) {
        int d = dst[e];
        int p = atomicAdd(&g_cursor[d], 1);
        g_col[p] = src[e];
    }
}

// ---------------- tensor-core GEMM (bf16x2 split, m16n8k16) -----------------
// hs[m,:] = fp16( (relu(bn(A[m,:])) @ W) * dinv[m] ); bn from gsum/gsq inline.
// Block tile 128(M) x 128(N), K-tile 16, 512 threads (16 warps, warp 32x32).

__device__ __forceinline__ void bsplit2(float x0, float x1, unsigned& hi, unsigned& lo) {
    __nv_bfloat16 h0 = __float2bfloat16(x0);
    __nv_bfloat16 h1 = __float2bfloat16(x1);
    float r0 = x0 - __bfloat162float(h0);
    float r1 = x1 - __bfloat162float(h1);
    __nv_bfloat16 l0 = __float2bfloat16(r0);
    __nv_bfloat16 l1 = __float2bfloat16(r1);
    hi = ((unsigned)__bfloat16_as_ushort(h1) << 16) | (unsigned)__bfloat16_as_ushort(h0);
    lo = ((unsigned)__bfloat16_as_ushort(l1) << 16) | (unsigned)__bfloat16_as_ushort(l0);
}

#define MMA_BF16(C, a0, a1, a2, a3, b0, b1)                                        \
    asm volatile(                                                                  \
        "mma.sync.aligned.m16n8k16.row.col.f32.bf16.bf16.f32 "                     \
        "{%0,%1,%2,%3},{%4,%5,%6,%7},{%8,%9},{%0,%1,%2,%3};"                       \
        : "+f"((C)[0]), "+f"((C)[1]), "+f"((C)[2]), "+f"((C)[3])                   \
        : "r"(a0), "r"(a1), "r"(a2), "r"(a3), "r"(b0), "r"(b1))

#define SA 136   // stride ≡ 8 (mod 32) → conflict-free fragment reads

__global__ __launch_bounds__(512) void k_gemm(
    const float* __restrict__ A_in, const float* __restrict__ W, int M, int K,
    const float* __restrict__ gsum, const float* __restrict__ gsq,
    const float* __restrict__ gamma, const float* __restrict__ beta) {
    const float* __restrict__ A = A_in ? A_in : g_agg;
    __shared__ unsigned sAh[8 * SA], sAl[8 * SA], sBh[8 * SA], sBl[8 * SA];
    __shared__ float sa[128], sc[128];

    int tid = threadIdx.x, lane = tid & 31, warp = tid >> 5;
    int use_bn = (gsum != nullptr);
    if (use_bn && tid < 128) {
        float mean = gsum[tid] * (1.0f / (float)NN);
        float var = gsq[tid] * (1.0f / (float)NN) - mean * mean;
        float a = gamma[tid] * rsqrtf(var + BN_EPS);
        sa[tid] = a;
        sc[tid] = beta[tid] - mean * a;
    }
    __syncthreads();

    int row0 = blockIdx.x * 128;
    int wm = (warp >> 2) * 32;
    int wn = (warp & 3) * 32;

    float acc[2][4][4];
    #pragma unroll
    for (int mi = 0; mi < 2; mi++)
        #pragma unroll
        for (int ni = 0; ni < 4; ni++)
            #pragma unroll
            for (int q = 0; q < 4; q++) acc[mi][ni][q] = 0.f;

    for (int k0 = 0; k0 < K; k0 += 16) {
        // ---- A tile (128 x 16): 1 float4 per thread ----
        {
            int m = tid >> 2, kv = (tid & 3) * 4, gm = row0 + m;
            float4 v = make_float4(0.f, 0.f, 0.f, 0.f);
            if (gm < M) v = *(const float4*)&A[(size_t)gm * K + k0 + kv];
            float e[4] = {v.x, v.y, v.z, v.w};
            if (use_bn) {
                #pragma unroll
                for (int q = 0; q < 4; q++) {
                    int kb = k0 + kv + q;
                    e[q] = fmaxf(fmaf(e[q], sa[kb], sc[kb]), 0.f);
                }
            }
            unsigned h0, l0, h1, l1;
            bsplit2(e[0], e[1], h0, l0);
            bsplit2(e[2], e[3], h1, l1);
            int k2 = kv >> 1;
            sAh[k2 * SA + m] = h0;       sAl[k2 * SA + m] = l0;
            sAh[(k2 + 1) * SA + m] = h1; sAl[(k2 + 1) * SA + m] = l1;
        }
        // ---- B tile (16 x 128): 2 cols x 2 rows per thread ----
        {
            int k2 = tid >> 6, n2 = (tid & 63) * 2;
            float2 w0 = *(const float2*)&W[(size_t)(k0 + k2 * 2) * 128 + n2];
            float2 w1 = *(const float2*)&W[(size_t)(k0 + k2 * 2 + 1) * 128 + n2];
            unsigned h, l;
            bsplit2(w0.x, w1.x, h, l);
            sBh[k2 * SA + n2] = h; sBl[k2 * SA + n2] = l;
            bsplit2(w0.y, w1.y, h, l);
            sBh[k2 * SA + n2 + 1] = h; sBl[k2 * SA + n2 + 1] = l;
        }
        __syncthreads();

        unsigned ah[2][4], al[2][4];
        int kq = lane & 3;
        #pragma unroll
        for (int mi = 0; mi < 2; mi++) {
            int r = wm + mi * 16 + (lane >> 2);
            ah[mi][0] = sAh[kq * SA + r];       ah[mi][1] = sAh[kq * SA + r + 8];
            ah[mi][2] = sAh[(kq + 4) * SA + r]; ah[mi][3] = sAh[(kq + 4) * SA + r + 8];
            al[mi][0] = sAl[kq * SA + r];       al[mi][1] = sAl[kq * SA + r + 8];
            al[mi][2] = sAl[(kq + 4) * SA + r]; al[mi][3] = sAl[(kq + 4) * SA + r + 8];
        }
        #pragma unroll
        for (int ni = 0; ni < 4; ni++) {
            int n = wn + ni * 8 + (lane >> 2);
            unsigned bh0 = sBh[kq * SA + n], bh1 = sBh[(kq + 4) * SA + n];
            unsigned bl0 = sBl[kq * SA + n], bl1 = sBl[(kq + 4) * SA + n];
            #pragma unroll
            for (int mi = 0; mi < 2; mi++) {
                MMA_BF16(acc[mi][ni], ah[mi][0], ah[mi][1], ah[mi][2], ah[mi][3], bh0, bh1);
                MMA_BF16(acc[mi][ni], ah[mi][0], ah[mi][1], ah[mi][2], ah[mi][3], bl0, bl1);
                MMA_BF16(acc[mi][ni], al[mi][0], al[mi][1], al[mi][2], al[mi][3], bh0, bh1);
            }
        }
        __syncthreads();
    }

    // ---- epilogue: scale by dinv[row], store fp16 (half2) ----
    #pragma unroll
    for (int mi = 0; mi < 2; mi++) {
        int r0 = row0 + wm + mi * 16 + (lane >> 2);
        int r1 = r0 + 8;
        float d0 = (r0 < M) ? g_dinv[r0] : 0.f;
        float d1 = (r1 < M) ? g_dinv[r1] : 0.f;
        #pragma unroll
        for (int ni = 0; ni < 4; ni++) {
            int nc = wn + ni * 8 + (lane & 3) * 2;
            if (r0 < M)
                *(__half2*)&g_hs[(size_t)r0 * 128 + nc] =
                    __floats2half2_rn(acc[mi][ni][0] * d0, acc[mi][ni][1] * d0);
            if (r1 < M)
                *(__half2*)&g_hs[(size_t)r1 * 128 + nc] =
                    __floats2half2_rn(acc[mi][ni][2] * d1, acc[mi][ni][3] * d1);
        }
    }
}

// ---------------- aggregation + BN stats (4 nodes per warp, fp16 gather) ----
__device__ __forceinline__ void acc_u2(float4& a, uint2 u) {
    float2 f0 = __half22float2(*reinterpret_cast<__half2*>(&u.x));
    float2 f1 = __half22float2(*reinterpret_cast<__half2*>(&u.y));
    a.x += f0.x; a.y += f0.y; a.z += f1.x; a.w += f1.y;
}

__global__ void k_agg(const float* __restrict__ b,
                      float* __restrict__ gsum, float* __restrict__ gsq) {
    __shared__ float s_sum[128];
    __shared__ float s_sq[128];
    if (threadIdx.x < 128) { s_sum[threadIdx.x] = 0.f; s_sq[threadIdx.x] = 0.f; }
    __syncthreads();

    int warp = threadIdx.x >> 5;
    int lane = threadIdx.x & 31;
    const uint2* __restrict__ hs2 = (const uint2*)g_hs;   // 32 uint2 per row
    float4 bb = ((const float4*)b)[lane];
    float4 ss = make_float4(0, 0, 0, 0), qq = make_float4(0, 0, 0, 0);

    int i0 = (blockIdx.x * 8 + warp) * 4;
    #pragma unroll
    for (int t = 0; t < 4; t++) {
        int i = i0 + t;
        if (i >= NN) break;
        float4 a0 = make_float4(0, 0, 0, 0);
        float4 a1 = make_float4(0, 0, 0, 0);
        float4 a2 = make_float4(0, 0, 0, 0);
        float4 a3 = make_float4(0, 0, 0, 0);
        acc_u2(a0, hs2[(size_t)i * 32 + lane]);   // self term
        int s = g_rowptr[i], e = g_rowptr[i + 1];
        int j = s;
        for (; j + 4 <= e; j += 4) {
            int c0 = g_col[j], c1 = g_col[j + 1], c2 = g_col[j + 2], c3 = g_col[j + 3];
            uint2 v0 = hs2[(size_t)c0 * 32 + lane];
            uint2 v1 = hs2[(size_t)c1 * 32 + lane];
            uint2 v2 = hs2[(size_t)c2 * 32 + lane];
            uint2 v3 = hs2[(size_t)c3 * 32 + lane];
            acc_u2(a0, v0); acc_u2(a1, v1); acc_u2(a2, v2); acc_u2(a3, v3);
        }
        for (; j < e; j++) {
            int c = g_col[j];
            acc_u2(a0, hs2[(size_t)c * 32 + lane]);
        }
        float di = g_dinv[i];
        float4 o;
        o.x = di * ((a0.x + a1.x) + (a2.x + a3.x)) + bb.x;
        o.y = di * ((a0.y + a1.y) + (a2.y + a3.y)) + bb.y;
        o.z = di * ((a0.z + a1.z) + (a2.z + a3.z)) + bb.z;
        o.w = di * ((a0.w + a1.w) + (a2.w + a3.w)) + bb.w;
        ((float4*)g_agg)[(size_t)i * 32 + lane] = o;
        ss.x += o.x; ss.y += o.y; ss.z += o.z; ss.w += o.w;
        qq.x += o.x * o.x; qq.y += o.y * o.y; qq.z += o.z * o.z; qq.w += o.w * o.w;
    }

    int f = lane * 4;
    atomicAdd(&s_sum[f + 0], ss.x); atomicAdd(&s_sq[f + 0], qq.x);
    atomicAdd(&s_sum[f + 1], ss.y); atomicAdd(&s_sq[f + 1], qq.y);
    atomicAdd(&s_sum[f + 2], ss.z); atomicAdd(&s_sq[f + 2], qq.z);
    atomicAdd(&s_sum[f + 3], ss.w); atomicAdd(&s_sq[f + 3], qq.w);
    __syncthreads();
    if (threadIdx.x < 128) {
        atomicAdd(&gsum[threadIdx.x], s_sum[threadIdx.x]);
        atomicAdd(&gsq[threadIdx.x], s_sq[threadIdx.x]);
    }
}

// ---------------- pooling (layer-3 BN+ReLU inline, BN computed in-block) ----
__global__ void k_pool(const int* __restrict__ batch,
                       const float* __restrict__ gsum, const float* __restrict__ gsq,
                       const float* __restrict__ gamma, const float* __restrict__ beta) {
    __shared__ float sa[128], sc[128];
    if (threadIdx.x < 128) {
        float mean = gsum[threadIdx.x] * (1.0f / (float)NN);
        float var = gsq[threadIdx.x] * (1.0f / (float)NN) - mean * mean;
        float a = gamma[threadIdx.x] * rsqrtf(var + BN_EPS);
        sa[threadIdx.x] = a;
        sc[threadIdx.x] = beta[threadIdx.x] - mean * a;
    }
    __syncthreads();

    int warp = threadIdx.x >> 5;
    int lane = threadIdx.x & 31;
    int i0 = blockIdx.x * 256 + warp * 32;
    int f = lane * 4;
    float a0 = sa[f + 0], a1 = sa[f + 1], a2 = sa[f + 2], a3 = sa[f + 3];
    float c0 = sc[f + 0], c1 = sc[f + 1], c2 = sc[f + 2], c3 = sc[f + 3];

    float4 acc = make_float4(0, 0, 0, 0);
    int cur = -1, run = 0;
    for (int t = 0; t < 32; t++) {
        int i = i0 + t;
        if (i >= NN) break;
        int g = batch[i];
        if (g != cur) {
            if (cur >= 0) {
                int base = cur * 128 + f;
                atomicAdd(&g_pool[base + 0], acc.x);
                atomicAdd(&g_pool[base + 1], acc.y);
                atomicAdd(&g_pool[base + 2], acc.z);
                atomicAdd(&g_pool[base + 3], acc.w);
                if (lane == 0) atomicAdd(&g_cnt[cur], (float)run);
            }
            cur = g; run = 0;
            acc = make_float4(0, 0, 0, 0);
        }
        float4 v = ((const float4*)g_agg)[(size_t)i * 32 + lane];
        acc.x += fmaxf(fmaf(v.x, a0, c0), 0.f);
        acc.y += fmaxf(fmaf(v.y, a1, c1), 0.f);
        acc.z += fmaxf(fmaf(v.z, a2, c2), 0.f);
        acc.w += fmaxf(fmaf(v.w, a3, c3), 0.f);
        run++;
    }
    if (cur >= 0) {
        int base = cur * 128 + f;
        atomicAdd(&g_pool[base + 0], acc.x);
        atomicAdd(&g_pool[base + 1], acc.y);
        atomicAdd(&g_pool[base + 2], acc.z);
        atomicAdd(&g_pool[base + 3], acc.w);
        if (lane == 0) atomicAdd(&g_cnt[cur], (float)run);
    }
}

// one block per graph: FC1 (128->256, relu) then FC2 (256->10)
__global__ void k_fc(const float* __restrict__ Wf1, const float* __restrict__ bf1,
                     const float* __restrict__ Wf2, const float* __restrict__ bf2,
                     float* __restrict__ out) {
    __shared__ float sp[128];
    __shared__ float sz[256];
    int g = blockIdx.x;
    int t = threadIdx.x;
    if (t < 128) {
        float cnt = fmaxf(g_cnt[g], 1.0f);
        sp[t] = g_pool[g * 128 + t] / cnt;
    }
    __syncthreads();
    float acc = bf1[t];
    #pragma unroll 8
    for (int k = 0; k < 128; k++) acc = fmaf(sp[k], Wf1[k * 256 + t], acc);
    sz[t] = fmaxf(acc, 0.f);
    __syncthreads();
    if (t < 10) {
        float o = bf2[t];
        #pragma unroll 8
        for (int k = 0; k < 256; k++) o = fmaf(sz[k], Wf2[k * 10 + t], o);
        out[g * 10 + t] = o;
    }
}

// ---------------- launch ------------------------------------------------------
extern "C" void kernel_launch(void* const* d_in, const int* in_sizes, int n_in,
                              void* d_out, int out_size) {
    const float* x     = (const float*)d_in[0];
    const int*   ei    = (const int*)d_in[1];
    const int*   batch = (const int*)d_in[2];
    const float* W1 = (const float*)d_in[3];
    const float* b1 = (const float*)d_in[4];
    const float* g1 = (const float*)d_in[5];
    const float* be1 = (const float*)d_in[6];
    const float* W2 = (const float*)d_in[7];
    const float* b2 = (const float*)d_in[8];
    const float* g2 = (const float*)d_in[9];
    const float* be2 = (const float*)d_in[10];
    const float* W3 = (const float*)d_in[11];
    const float* b3 = (const float*)d_in[12];
    const float* g3 = (const float*)d_in[13];
    const float* be3 = (const float*)d_in[14];
    const float* Wf1 = (const float*)d_in[15];
    const float* bf1 = (const float*)d_in[16];
    const float* Wf2 = (const float*)d_in[17];
    const float* bf2 = (const float*)d_in[18];
    float* out = (float*)d_out;

    const int* src = ei;
    const int* dst = ei + EE;

    float* sum0; float* sq0; float* sum1; float* sq1; float* sum2; float* sq2;
    cudaGetSymbolAddress((void**)&sum0, g_sumA);
    cudaGetSymbolAddress((void**)&sq0, g_sqA);
    sum1 = sum0 + 128; sum2 = sum0 + 256;
    sq1 = sq0 + 128; sq2 = sq0 + 256;

    // preprocessing
    k_init<<<(NN + 255) / 256, 256>>>();
    k_deg_count<<<(EE + 255) / 256, 256>>>(dst);
    k_scan<<<1, 1024>>>();
    k_fill<<<(EE + 255) / 256, 256>>>(src, dst);

    const int gemm_grid = (NN + 127) / 128;
    const int agg_grid = (NN + 31) / 32;

    // layer 1 (K=96, input x, no BN)
    k_gemm<<<gemm_grid, 512>>>(x, W1, NN, 96, nullptr, nullptr, nullptr, nullptr);
    k_agg<<<agg_grid, 256>>>(b1, sum0, sq0);

    // layer 2 (BN1+ReLU fused into A-load)
    k_gemm<<<gemm_grid, 512>>>(nullptr, W2, NN, 128, sum0, sq0, g1, be1);
    k_agg<<<agg_grid, 256>>>(b2, sum1, sq1);

    // layer 3
    k_gemm<<<gemm_grid, 512>>>(nullptr, W3, NN, 128, sum1, sq1, g2, be2);
    k_agg<<<agg_grid, 256>>>(b3, sum2, sq2);

    // pool (BN3+ReLU inline) + FC head
    k_pool<<<(NN + 255) / 256, 256>>>(batch, sum2, sq2, g3, be3);
    k_fc<<<GG, 256>>>(Wf1, bf1, Wf2, bf2, out);
}